// round 15
// baseline (speedup 1.0000x reference)
#include <cuda_runtime.h>
#include <cuda_bf16.h>
#include <math.h>
#include <stdint.h>

#define D_MODEL 2048
#define NHEADS  16
#define DPH     128
#define DFF     8192
#define BATCH   2
#define SEQ     2048
#define NROWS   (BATCH*SEQ)   // 4096
#define LDQKV   6144

// ---------------- scratch (device globals; no allocation allowed) ----------
__device__ float g_qkv[NROWS*LDQKV];            // q|k|v concatenated, fp32

__device__ __nv_bfloat16 g_xnh [NROWS*D_MODEL];
__device__ __nv_bfloat16 g_xnl [NROWS*D_MODEL];
__device__ __nv_bfloat16 g_hh  [NROWS*DFF];
__device__ __nv_bfloat16 g_hl  [NROWS*DFF];
__device__ __nv_bfloat16 g_atth[NROWS*D_MODEL];
__device__ __nv_bfloat16 g_attl[NROWS*D_MODEL];
// transposed weights [N,K] bf16 hi/lo
__device__ __nv_bfloat16 g_wqkvth[3*D_MODEL*D_MODEL];
__device__ __nv_bfloat16 g_wqkvtl[3*D_MODEL*D_MODEL];
__device__ __nv_bfloat16 g_woth[D_MODEL*D_MODEL];
__device__ __nv_bfloat16 g_wotl[D_MODEL*D_MODEL];
__device__ __nv_bfloat16 g_fith[DFF*D_MODEL];   // fc_in^T  [8192,2048]
__device__ __nv_bfloat16 g_fitl[DFF*D_MODEL];
__device__ __nv_bfloat16 g_foth[D_MODEL*DFF];   // fc_out^T [2048,8192]
__device__ __nv_bfloat16 g_fotl[D_MODEL*DFF];

// ============================ PTX helpers ===================================
__device__ __forceinline__ uint32_t smem_u32(const void* p) {
    uint32_t a;
    asm("{ .reg .u64 t; cvta.to.shared.u64 t, %1; cvt.u32.u64 %0, t; }"
        : "=r"(a) : "l"(p));
    return a;
}
__device__ __forceinline__ void cp16(uint32_t dst, const void* src) {
    asm volatile("cp.async.cg.shared.global [%0], [%1], 16;" :: "r"(dst), "l"(src));
}
__device__ __forceinline__ void cp_commit() {
    asm volatile("cp.async.commit_group;" ::: "memory");
}
__device__ __forceinline__ void ldsm4(uint32_t& r0, uint32_t& r1, uint32_t& r2,
                                      uint32_t& r3, uint32_t addr) {
    asm volatile("ldmatrix.sync.aligned.m8n8.x4.shared.b16 {%0,%1,%2,%3}, [%4];"
                 : "=r"(r0), "=r"(r1), "=r"(r2), "=r"(r3) : "r"(addr));
}
// NOTE: non-volatile on purpose — outputs are registers only; lets the
// compiler schedule/interleave independent MMAs.
__device__ __forceinline__ void mma16816(float* c, const uint32_t* a, const uint32_t* b) {
    asm("mma.sync.aligned.m16n8k16.row.col.f32.bf16.bf16.f32 "
        "{%0,%1,%2,%3}, {%4,%5,%6,%7}, {%8,%9}, {%0,%1,%2,%3};"
        : "+f"(c[0]), "+f"(c[1]), "+f"(c[2]), "+f"(c[3])
        : "r"(a[0]), "r"(a[1]), "r"(a[2]), "r"(a[3]), "r"(b[0]), "r"(b[1]));
}
__device__ __forceinline__ float gelu_f(float x) {
    float x3 = x * x * x;
    return 0.5f * x * (1.0f + tanhf(0.7978845608028654f * (x + 0.044715f * x3)));
}

// ============================ HMMA GEMM =====================================
// C[M,N] = (Ah+Al)[M,K] @ (Bh+Bl)[N,K]^T   (3-term split bf16, fp32 accum)
// BM=128, BN=128, BK=32, 2-stage cp.async pipeline (80KB -> 2 CTAs/SM),
// 8 warps (64x32 each). Term-major MMA order: RAW distance 4 between
// same-accumulator HMMAs (was 1 -> latency-serialized).
#define ROWB     80
#define TILE_B   (128 * ROWB)
#define STAGE_B  (4 * TILE_B)
#define NSTAGE   2
#define GEMM_SMEM (NSTAGE * STAGE_B)   // 81920 B

// MODE: 0 = plain fp32 C, 1 = bias+gelu -> bf16 hi/lo (Ch,Cl), 2 = bias -> C,
//       3 = accumulate into C
template<int MODE>
__global__ __launch_bounds__(256, 2) void gemm_mma(
    const __nv_bfloat16* __restrict__ Ah, const __nv_bfloat16* __restrict__ Al,
    const __nv_bfloat16* __restrict__ Bh, const __nv_bfloat16* __restrict__ Bl,
    const float* __restrict__ bias, float* __restrict__ C,
    __nv_bfloat16* __restrict__ Ch, __nv_bfloat16* __restrict__ Cl,
    int M, int N, int K)
{
    extern __shared__ __align__(128) char smem[];
    uint32_t sb = smem_u32(smem);
    int t    = threadIdx.x;
    int lane = t & 31;
    int wid  = t >> 5;
    int warp_m = wid >> 2;
    int warp_n = wid & 3;
    int row0 = blockIdx.y << 7;
    int col0 = blockIdx.x << 7;

    float acc[4][4][4];
    #pragma unroll
    for (int i = 0; i < 4; i++)
        #pragma unroll
        for (int j = 0; j < 4; j++)
            #pragma unroll
            for (int e = 0; e < 4; e++) acc[i][j][e] = 0.0f;

    const int T = K >> 5;

    // loader: 8 precomputed pointers advanced by +=32 per stage
    int r_ = t >> 2, c_ = t & 3;
    uint32_t so0 = r_ * ROWB + c_ * 16;
    uint32_t so1 = (r_ + 64) * ROWB + c_ * 16;
    const __nv_bfloat16* pAh0 = Ah + (size_t)(row0 + r_) * K + c_ * 8;
    const __nv_bfloat16* pAh1 = pAh0 + (size_t)64 * K;
    const __nv_bfloat16* pAl0 = Al + (size_t)(row0 + r_) * K + c_ * 8;
    const __nv_bfloat16* pAl1 = pAl0 + (size_t)64 * K;
    const __nv_bfloat16* pBh0 = Bh + (size_t)(col0 + r_) * K + c_ * 8;
    const __nv_bfloat16* pBh1 = pBh0 + (size_t)64 * K;
    const __nv_bfloat16* pBl0 = Bl + (size_t)(col0 + r_) * K + c_ * 8;
    const __nv_bfloat16* pBl1 = pBl0 + (size_t)64 * K;

    #define LOAD_STAGE(P) do {                                                \
        uint32_t b_ = sb + (P) * STAGE_B;                                     \
        cp16(b_ + so0,               pAh0);  cp16(b_ + so1,               pAh1); \
        cp16(b_ + TILE_B + so0,      pAl0);  cp16(b_ + TILE_B + so1,      pAl1); \
        cp16(b_ + 2*TILE_B + so0,    pBh0);  cp16(b_ + 2*TILE_B + so1,    pBh1); \
        cp16(b_ + 3*TILE_B + so0,    pBl0);  cp16(b_ + 3*TILE_B + so1,    pBl1); \
        cp_commit();                                                          \
        pAh0 += 32; pAh1 += 32; pAl0 += 32; pAl1 += 32;                       \
        pBh0 += 32; pBh1 += 32; pBl0 += 32; pBl1 += 32;                       \
    } while (0)

    LOAD_STAGE(0);
    LOAD_STAGE(1);

    int lrow = lane & 15, lcol = lane >> 4;

    for (int tt = 0; tt < T; tt++) {
        if (tt + 1 < T) asm volatile("cp.async.wait_group 1;" ::: "memory");
        else            asm volatile("cp.async.wait_group 0;" ::: "memory");
        __syncthreads();

        uint32_t st = sb + (tt & 1) * STAGE_B;
        uint32_t sAh = st;
        uint32_t sAl = st + TILE_B;
        uint32_t sBh = st + 2 * TILE_B;
        uint32_t sBl = st + 3 * TILE_B;

        #pragma unroll
        for (int ks = 0; ks < 2; ks++) {
            uint32_t koff = ks * 32 + lcol * 16;
            uint32_t bh[4][2], bl[4][2];
            #pragma unroll
            for (int bt = 0; bt < 2; bt++) {
                uint32_t rb = (warp_n * 32 + bt * 16 + lrow) * ROWB + koff;
                uint32_t r0, r1, r2, r3;
                ldsm4(r0, r1, r2, r3, sBh + rb);
                bh[bt*2][0] = r0; bh[bt*2][1] = r2;
                bh[bt*2+1][0] = r1; bh[bt*2+1][1] = r3;
                ldsm4(r0, r1, r2, r3, sBl + rb);
                bl[bt*2][0] = r0; bl[bt*2][1] = r2;
                bl[bt*2+1][0] = r1; bl[bt*2+1][1] = r3;
            }

            // software-pipelined A fragments: a[buf][0]=hi, a[buf][1]=lo
            uint32_t a[2][2][4];
            {
                uint32_t ra = (warp_m * 64 + lrow) * ROWB + koff;
                ldsm4(a[0][0][0], a[0][0][1], a[0][0][2], a[0][0][3], sAh + ra);
                ldsm4(a[0][1][0], a[0][1][1], a[0][1][2], a[0][1][3], sAl + ra);
            }
            #pragma unroll
            for (int mt = 0; mt < 4; mt++) {
                if (mt < 3) {
                    uint32_t ra = (warp_m * 64 + (mt + 1) * 16 + lrow) * ROWB + koff;
                    int nb = (mt + 1) & 1;
                    ldsm4(a[nb][0][0], a[nb][0][1], a[nb][0][2], a[nb][0][3], sAh + ra);
                    ldsm4(a[nb][1][0], a[nb][1][1], a[nb][1][2], a[nb][1][3], sAl + ra);
                }
                const uint32_t* ah = a[mt & 1][0];
                const uint32_t* al = a[mt & 1][1];
                // term-major: consecutive MMAs hit different accumulators
                // (RAW distance 4); per-acc term order hh->hl->lh unchanged.
                #pragma unroll
                for (int nt = 0; nt < 4; nt++) mma16816(acc[mt][nt], ah, bh[nt]);
                #pragma unroll
                for (int nt = 0; nt < 4; nt++) mma16816(acc[mt][nt], ah, bl[nt]);
                #pragma unroll
                for (int nt = 0; nt < 4; nt++) mma16816(acc[mt][nt], al, bh[nt]);
            }
        }
        __syncthreads();   // compute on this buffer done -> safe to refill
        if (tt + 2 < T) LOAD_STAGE(tt & 1);
    }

    // epilogue
    #pragma unroll
    for (int mt = 0; mt < 4; mt++) {
        int r0g = row0 + warp_m * 64 + mt * 16 + (lane >> 2);
        #pragma unroll
        for (int nt = 0; nt < 4; nt++) {
            int cg = col0 + warp_n * 32 + nt * 8 + (lane & 3) * 2;
            float b0 = 0.f, b1 = 0.f;
            if (MODE == 1 || MODE == 2) { b0 = bias[cg]; b1 = bias[cg + 1]; }
            float v0 = acc[mt][nt][0] + b0;
            float v1 = acc[mt][nt][1] + b1;
            float v2 = acc[mt][nt][2] + b0;
            float v3 = acc[mt][nt][3] + b1;
            if (MODE == 1) {
                v0 = gelu_f(v0); v1 = gelu_f(v1); v2 = gelu_f(v2); v3 = gelu_f(v3);
                size_t i0 = (size_t)r0g * N + cg;
                size_t i1 = (size_t)(r0g + 8) * N + cg;
                __nv_bfloat16 h0 = __float2bfloat16(v0), h1 = __float2bfloat16(v1);
                __nv_bfloat16 h2 = __float2bfloat16(v2), h3 = __float2bfloat16(v3);
                *(__nv_bfloat162*)(Ch + i0) = __halves2bfloat162(h0, h1);
                *(__nv_bfloat162*)(Ch + i1) = __halves2bfloat162(h2, h3);
                *(__nv_bfloat162*)(Cl + i0) = __halves2bfloat162(
                    __float2bfloat16(v0 - __bfloat162float(h0)),
                    __float2bfloat16(v1 - __bfloat162float(h1)));
                *(__nv_bfloat162*)(Cl + i1) = __halves2bfloat162(
                    __float2bfloat16(v2 - __bfloat162float(h2)),
                    __float2bfloat16(v3 - __bfloat162float(h3)));
            } else {
                float* p0 = C + (size_t)r0g * N + cg;
                float* p1 = C + (size_t)(r0g + 8) * N + cg;
                if (MODE == 3) { v0 += p0[0]; v1 += p0[1]; v2 += p1[0]; v3 += p1[1]; }
                p0[0] = v0; p0[1] = v1;
                p1[0] = v2; p1[1] = v3;
            }
        }
    }
}

// ======================= transpose+split: W[K,N] -> Th/Tl[N,K] ==============
__global__ __launch_bounds__(256) void transpose_split_kernel(
    const float* __restrict__ W, __nv_bfloat16* __restrict__ Th,
    __nv_bfloat16* __restrict__ Tl, int K, int N)
{
    __shared__ float tile[32][33];
    int bx = blockIdx.x, by = blockIdx.y;
    int tx = threadIdx.x, ty = threadIdx.y;
    int n_in = bx * 32 + tx;
    for (int j = ty; j < 32; j += 8)
        tile[j][tx] = W[(size_t)(by * 32 + j) * N + n_in];
    __syncthreads();
    for (int jj = ty; jj < 32; jj += 8) {
        float v = tile[tx][jj];
        size_t o = (size_t)(bx * 32 + jj) * K + by * 32 + tx;
        __nv_bfloat16 hi = __float2bfloat16(v);
        Th[o] = hi;
        Tl[o] = __float2bfloat16(v - __bfloat162float(hi));
    }
}

// ---------------- LayerNorm + split (bf16 hi/lo out) ------------------------
__global__ __launch_bounds__(256) void ln_split_kernel(
    const float* __restrict__ x, const float* __restrict__ sc,
    const float* __restrict__ of,
    __nv_bfloat16* __restrict__ yh, __nv_bfloat16* __restrict__ yl)
{
    int row = blockIdx.x;
    int t   = threadIdx.x;
    const float4* xr = (const float4*)(x + (size_t)row * D_MODEL);
    float4 v0 = xr[t];
    float4 v1 = xr[t + 256];
    float s  = v0.x + v0.y + v0.z + v0.w + v1.x + v1.y + v1.z + v1.w;
    float ss = v0.x*v0.x + v0.y*v0.y + v0.z*v0.z + v0.w*v0.w
             + v1.x*v1.x + v1.y*v1.y + v1.z*v1.z + v1.w*v1.w;
    __shared__ float r1[256];
    __shared__ float r2[256];
    r1[t] = s; r2[t] = ss;
    __syncthreads();
    for (int o2 = 128; o2 > 0; o2 >>= 1) {
        if (t < o2) { r1[t] += r1[t + o2]; r2[t] += r2[t + o2]; }
        __syncthreads();
    }
    float mean = r1[0] * (1.0f / D_MODEL);
    float var  = r2[0] * (1.0f / D_MODEL) - mean * mean;
    float rstd = rsqrtf(var + 1e-5f);

    float4 s0 = ((const float4*)sc)[t], s1 = ((const float4*)sc)[t + 256];
    float4 o0 = ((const float4*)of)[t], o1 = ((const float4*)of)[t + 256];
    float y[8];
    y[0] = s0.x * rstd * (v0.x - mean) + o0.x;
    y[1] = s0.y * rstd * (v0.y - mean) + o0.y;
    y[2] = s0.z * rstd * (v0.z - mean) + o0.z;
    y[3] = s0.w * rstd * (v0.w - mean) + o0.w;
    y[4] = s1.x * rstd * (v1.x - mean) + o1.x;
    y[5] = s1.y * rstd * (v1.y - mean) + o1.y;
    y[6] = s1.z * rstd * (v1.z - mean) + o1.z;
    y[7] = s1.w * rstd * (v1.w - mean) + o1.w;

    __nv_bfloat162* H = (__nv_bfloat162*)(yh + (size_t)row * D_MODEL);
    __nv_bfloat162* L = (__nv_bfloat162*)(yl + (size_t)row * D_MODEL);
    #pragma unroll
    for (int g = 0; g < 2; g++) {
        int base2 = g * 512 + 2 * t;
        #pragma unroll
        for (int p = 0; p < 2; p++) {
            float a = y[g*4 + 2*p], b = y[g*4 + 2*p + 1];
            __nv_bfloat16 ha = __float2bfloat16(a), hb = __float2bfloat16(b);
            H[base2 + p] = __halves2bfloat162(ha, hb);
            L[base2 + p] = __halves2bfloat162(
                __float2bfloat16(a - __bfloat162float(ha)),
                __float2bfloat16(b - __bfloat162float(hb)));
        }
    }
}

// ---------------- RoPE on combined qkv (cols [0,4096)), in place -----------
__global__ __launch_bounds__(256) void rope_kernel(float* __restrict__ qkv)
{
    __shared__ double freq[64];
    int t = threadIdx.x;
    if (t < 64) freq[t] = pow(10000.0, -2.0 * t / 128.0);
    __syncthreads();
    int idx = blockIdx.x * 256 + t;
    int row  = idx >> 11;
    int pr   = idx & 2047;
    int slot = pr >> 6;
    int j    = pr & 63;
    int pos  = row & (SEQ - 1);
    size_t base = (size_t)row * LDQKV + slot * DPH + 2 * j;
    double ang = fmod((double)pos * freq[j], 6.283185307179586476925287);
    float fa = (float)ang;
    float sn = sinf(fa), cs = cosf(fa);
    float x0 = qkv[base], x1 = qkv[base + 1];
    qkv[base]     = x0 * cs - x1 * sn;
    qkv[base + 1] = x1 * cs + x0 * sn;
}

// ---------------- Flash attention (causal, +bias), vectorized ---------------
// BK=16 keeps smem at 54.5KB.
#define BQ 64
#define BK 16
#define FLASH_SMEM ((64*132 + BK*128 + BK*128 + 64*17) * 4)

__global__ __launch_bounds__(64) void flash_kernel(
    const float* __restrict__ QKV, const float* __restrict__ bias,
    __nv_bfloat16* __restrict__ Oh, __nv_bfloat16* __restrict__ Ol)
{
    extern __shared__ float sm[];
    float* q_sh = sm;                    // 64 x 132
    float* k_sh = q_sh + 64 * 132;       // BK x 128
    float* v_sh = k_sh + BK * 128;       // BK x 128
    float* b_sh = v_sh + BK * 128;       // 64 x 17

    int t  = threadIdx.x;
    int q0 = blockIdx.x * BQ;
    int h  = blockIdx.y;
    int b  = blockIdx.z;
    size_t qb = (size_t)b * SEQ * LDQKV + (size_t)h * DPH;
    size_t kb_ = qb + 2048;
    size_t vb_ = qb + 4096;

    for (int c = t; c < 64 * 32; c += 64) {
        int r = c >> 5, cc = c & 31;
        *(float4*)&q_sh[r * 132 + cc * 4] =
            *(const float4*)&QKV[qb + (size_t)(q0 + r) * LDQKV + cc * 4];
    }

    int qg = q0 + t;
    float m = -1e30f, l = 0.0f;
    float o[DPH];
    #pragma unroll
    for (int d = 0; d < DPH; d++) o[d] = 0.0f;

    const float scale = 0.08838834764831845f;
    int ntiles = (q0 + BQ) / BK;

    for (int kt = 0; kt < ntiles; kt++) {
        int kbase = kt * BK;
        __syncthreads();
        for (int c = t; c < BK * 32; c += 64) {
            int r = c >> 5, cc = c & 31;
            *(float4*)&k_sh[r * 128 + cc * 4] =
                *(const float4*)&QKV[kb_ + (size_t)(kbase + r) * LDQKV + cc * 4];
            *(float4*)&v_sh[r * 128 + cc * 4] =
                *(const float4*)&QKV[vb_ + (size_t)(kbase + r) * LDQKV + cc * 4];
        }
        for (int i = t; i < BQ * BK; i += 64) {
            int r = i >> 4, c = i & 15;
            b_sh[r * 17 + c] = bias[(size_t)(q0 + r) * SEQ + kbase + c];
        }
        __syncthreads();

        float s[BK];
        #pragma unroll
        for (int j = 0; j < BK; j++) s[j] = 0.0f;
        const float4* q4 = (const float4*)&q_sh[t * 132];
        for (int dc = 0; dc < 32; dc++) {
            float4 qv = q4[dc];
            #pragma unroll
            for (int j = 0; j < BK; j++) {
                float4 kv = *(const float4*)&k_sh[j * 128 + dc * 4];
                s[j] += qv.x*kv.x + qv.y*kv.y + qv.z*kv.z + qv.w*kv.w;
            }
        }

        float tmax = -1e30f;
        #pragma unroll
        for (int j = 0; j < BK; j++) {
            float sv = (kbase + j <= qg) ? s[j] * scale + b_sh[t * 17 + j] : -1e30f;
            s[j] = sv;
            tmax = fmaxf(tmax, sv);
        }
        float mn   = fmaxf(m, tmax);
        float corr = expf(m - mn);
        float ps = 0.0f;
        #pragma unroll
        for (int j = 0; j < BK; j++) {
            float p = expf(s[j] - mn);
            s[j] = p;
            ps += p;
        }
        l = l * corr + ps;
        m = mn;
        #pragma unroll
        for (int d = 0; d < DPH; d++) o[d] *= corr;
        for (int j = 0; j < BK; j++) {
            float p = s[j];
            #pragma unroll
            for (int dc = 0; dc < 32; dc++) {
                float4 vv = *(const float4*)&v_sh[j * 128 + dc * 4];
                o[4*dc]   += p * vv.x;
                o[4*dc+1] += p * vv.y;
                o[4*dc+2] += p * vv.z;
                o[4*dc+3] += p * vv.w;
            }
        }
    }

    float inv = 1.0f / l;
    size_t ob = ((size_t)(b * SEQ + qg)) * D_MODEL + (size_t)h * DPH;
    __nv_bfloat162* OH = (__nv_bfloat162*)(Oh + ob);
    __nv_bfloat162* OL = (__nv_bfloat162*)(Ol + ob);
    #pragma unroll
    for (int dc = 0; dc < 64; dc++) {
        float a = o[2*dc] * inv, c = o[2*dc+1] * inv;
        __nv_bfloat16 ha = __float2bfloat16(a), hc = __float2bfloat16(c);
        OH[dc] = __halves2bfloat162(ha, hc);
        OL[dc] = __halves2bfloat162(
            __float2bfloat16(a - __bfloat162float(ha)),
            __float2bfloat16(c - __bfloat162float(hc)));
    }
}

// ---------------- launch ----------------------------------------------------
extern "C" void kernel_launch(void* const* d_in, const int* in_sizes, int n_in,
                              void* d_out, int out_size)
{
    const float* x         = (const float*)d_in[0];
    const float* attn_bias = (const float*)d_in[1];
    const float* ln_scale  = (const float*)d_in[2];
    const float* ln_offset = (const float*)d_in[3];
    const float* wq        = (const float*)d_in[4];
    const float* wk        = (const float*)d_in[5];
    const float* wv        = (const float*)d_in[6];
    const float* wo        = (const float*)d_in[7];
    const float* w_fc_in   = (const float*)d_in[8];
    const float* b_fc_in   = (const float*)d_in[9];
    const float* w_fc_out  = (const float*)d_in[10];
    const float* b_fc_out  = (const float*)d_in[11];
    float* out = (float*)d_out;

    float* qkv;
    cudaGetSymbolAddress((void**)&qkv, g_qkv);
    __nv_bfloat16 *xnh,*xnl,*hh,*hl,*atth,*attl;
    __nv_bfloat16 *wqkvth,*wqkvtl,*woth,*wotl,*fith,*fitl,*foth,*fotl;
    cudaGetSymbolAddress((void**)&xnh,    g_xnh);
    cudaGetSymbolAddress((void**)&xnl,    g_xnl);
    cudaGetSymbolAddress((void**)&hh,     g_hh);
    cudaGetSymbolAddress((void**)&hl,     g_hl);
    cudaGetSymbolAddress((void**)&atth,   g_atth);
    cudaGetSymbolAddress((void**)&attl,   g_attl);
    cudaGetSymbolAddress((void**)&wqkvth, g_wqkvth);
    cudaGetSymbolAddress((void**)&wqkvtl, g_wqkvtl);
    cudaGetSymbolAddress((void**)&woth,   g_woth);
    cudaGetSymbolAddress((void**)&wotl,   g_wotl);
    cudaGetSymbolAddress((void**)&fith,   g_fith);
    cudaGetSymbolAddress((void**)&fitl,   g_fitl);
    cudaGetSymbolAddress((void**)&foth,   g_foth);
    cudaGetSymbolAddress((void**)&fotl,   g_fotl);

    cudaFuncSetAttribute(gemm_mma<0>, cudaFuncAttributeMaxDynamicSharedMemorySize, GEMM_SMEM);
    cudaFuncSetAttribute(gemm_mma<1>, cudaFuncAttributeMaxDynamicSharedMemorySize, GEMM_SMEM);
    cudaFuncSetAttribute(gemm_mma<2>, cudaFuncAttributeMaxDynamicSharedMemorySize, GEMM_SMEM);
    cudaFuncSetAttribute(gemm_mma<3>, cudaFuncAttributeMaxDynamicSharedMemorySize, GEMM_SMEM);
    cudaFuncSetAttribute(flash_kernel, cudaFuncAttributeMaxDynamicSharedMemorySize, FLASH_SMEM);

    dim3 tb(32, 8);
    const int DD = D_MODEL * D_MODEL;

    // side stream + fork/join events (host objects only; graph-capture safe)
    cudaStream_t s2;
    cudaStreamCreate(&s2);
    cudaEvent_t ev_ln, ev_ffn;
    cudaEventCreateWithFlags(&ev_ln,  cudaEventDisableTiming);
    cudaEventCreateWithFlags(&ev_ffn, cudaEventDisableTiming);

    // ---- main stream: LN, then fork ----
    ln_split_kernel<<<NROWS, 256>>>(x, ln_scale, ln_offset, xnh, xnl);
    cudaEventRecord(ev_ln, 0);

    // ---- side stream: FFN weight transposes + FFN chain ----
    transpose_split_kernel<<<dim3(DFF/32, D_MODEL/32), tb, 0, s2>>>(w_fc_in,  fith, fitl, D_MODEL, DFF);
    transpose_split_kernel<<<dim3(D_MODEL/32, DFF/32), tb, 0, s2>>>(w_fc_out, foth, fotl, DFF, D_MODEL);
    cudaStreamWaitEvent(s2, ev_ln, 0);
    gemm_mma<1><<<dim3(DFF/128, NROWS/128), 256, GEMM_SMEM, s2>>>(
        xnh, xnl, fith, fitl, b_fc_in, nullptr, hh, hl, NROWS, DFF, D_MODEL);
    gemm_mma<2><<<dim3(D_MODEL/128, NROWS/128), 256, GEMM_SMEM, s2>>>(
        hh, hl, foth, fotl, b_fc_out, out, nullptr, nullptr, NROWS, D_MODEL, DFF);
    cudaEventRecord(ev_ffn, s2);

    // ---- main stream: attention chain ----
    transpose_split_kernel<<<dim3(D_MODEL/32, D_MODEL/32), tb>>>(wq, wqkvth,        wqkvtl,        D_MODEL, D_MODEL);
    transpose_split_kernel<<<dim3(D_MODEL/32, D_MODEL/32), tb>>>(wk, wqkvth + DD,   wqkvtl + DD,   D_MODEL, D_MODEL);
    transpose_split_kernel<<<dim3(D_MODEL/32, D_MODEL/32), tb>>>(wv, wqkvth + 2*DD, wqkvtl + 2*DD, D_MODEL, D_MODEL);
    transpose_split_kernel<<<dim3(D_MODEL/32, D_MODEL/32), tb>>>(wo, woth, wotl, D_MODEL, D_MODEL);

    gemm_mma<0><<<dim3(LDQKV/128, NROWS/128), 256, GEMM_SMEM>>>(
        xnh, xnl, wqkvth, wqkvtl, nullptr, qkv, nullptr, nullptr,
        NROWS, LDQKV, D_MODEL);
    rope_kernel<<<(NROWS * 2048) / 256, 256>>>(qkv);
    flash_kernel<<<dim3(SEQ / BQ, NHEADS, BATCH), 64, FLASH_SMEM>>>(
        qkv, attn_bias, atth, attl);

    // ---- join: WO GEMM accumulates into out (written by FFN-out) ----
    cudaStreamWaitEvent(0, ev_ffn, 0);
    gemm_mma<3><<<dim3(D_MODEL/128, NROWS/128), 256, GEMM_SMEM>>>(
        atth, attl, woth, wotl, nullptr, out, nullptr, nullptr, NROWS, D_MODEL, D_MODEL);

    cudaEventDestroy(ev_ln);
    cudaEventDestroy(ev_ffn);
    cudaStreamDestroy(s2);
}

// round 16
// speedup vs baseline: 1.0703x; 1.0703x over previous
#include <cuda_runtime.h>
#include <cuda_bf16.h>
#include <math.h>
#include <stdint.h>

#define D_MODEL 2048
#define NHEADS  16
#define DPH     128
#define DFF     8192
#define BATCH   2
#define SEQ     2048
#define NROWS   (BATCH*SEQ)   // 4096
#define LDQKV   6144

// ---------------- scratch (device globals; no allocation allowed) ----------
__device__ float g_qkv[NROWS*LDQKV];            // q|k|v concatenated, fp32

__device__ __nv_bfloat16 g_xnh [NROWS*D_MODEL];
__device__ __nv_bfloat16 g_xnl [NROWS*D_MODEL];
__device__ __nv_bfloat16 g_hh  [NROWS*DFF];
__device__ __nv_bfloat16 g_hl  [NROWS*DFF];
__device__ __nv_bfloat16 g_atth[NROWS*D_MODEL];
__device__ __nv_bfloat16 g_attl[NROWS*D_MODEL];
// transposed weights [N,K] bf16 hi/lo
__device__ __nv_bfloat16 g_wqkvth[3*D_MODEL*D_MODEL];
__device__ __nv_bfloat16 g_wqkvtl[3*D_MODEL*D_MODEL];
__device__ __nv_bfloat16 g_woth[D_MODEL*D_MODEL];
__device__ __nv_bfloat16 g_wotl[D_MODEL*D_MODEL];
__device__ __nv_bfloat16 g_fith[DFF*D_MODEL];   // fc_in^T  [8192,2048]
__device__ __nv_bfloat16 g_fitl[DFF*D_MODEL];
__device__ __nv_bfloat16 g_foth[D_MODEL*DFF];   // fc_out^T [2048,8192]
__device__ __nv_bfloat16 g_fotl[D_MODEL*DFF];

// ============================ PTX helpers ===================================
__device__ __forceinline__ uint32_t smem_u32(const void* p) {
    uint32_t a;
    asm("{ .reg .u64 t; cvta.to.shared.u64 t, %1; cvt.u32.u64 %0, t; }"
        : "=r"(a) : "l"(p));
    return a;
}
__device__ __forceinline__ void cp16(uint32_t dst, const void* src) {
    asm volatile("cp.async.cg.shared.global [%0], [%1], 16;" :: "r"(dst), "l"(src));
}
__device__ __forceinline__ void cp_commit() {
    asm volatile("cp.async.commit_group;" ::: "memory");
}
__device__ __forceinline__ void ldsm4(uint32_t& r0, uint32_t& r1, uint32_t& r2,
                                      uint32_t& r3, uint32_t addr) {
    asm volatile("ldmatrix.sync.aligned.m8n8.x4.shared.b16 {%0,%1,%2,%3}, [%4];"
                 : "=r"(r0), "=r"(r1), "=r"(r2), "=r"(r3) : "r"(addr));
}
__device__ __forceinline__ void mma16816(float* c, const uint32_t* a, const uint32_t* b) {
    asm volatile(
        "mma.sync.aligned.m16n8k16.row.col.f32.bf16.bf16.f32 "
        "{%0,%1,%2,%3}, {%4,%5,%6,%7}, {%8,%9}, {%0,%1,%2,%3};"
        : "+f"(c[0]), "+f"(c[1]), "+f"(c[2]), "+f"(c[3])
        : "r"(a[0]), "r"(a[1]), "r"(a[2]), "r"(a[3]), "r"(b[0]), "r"(b[1]));
}
__device__ __forceinline__ float gelu_f(float x) {
    float x3 = x * x * x;
    return 0.5f * x * (1.0f + tanhf(0.7978845608028654f * (x + 0.044715f * x3)));
}

// packed f32x2 (Blackwell sm_100+)
typedef unsigned long long u64t;
__device__ __forceinline__ u64t pack2(float lo, float hi) {
    u64t r;
    asm("mov.b64 %0, {%1,%2};" : "=l"(r) : "f"(lo), "f"(hi));
    return r;
}
__device__ __forceinline__ void unpack2(u64t v, float& lo, float& hi) {
    asm("mov.b64 {%0,%1}, %2;" : "=f"(lo), "=f"(hi) : "l"(v));
}
#define FMA2(d, a, b, c) asm("fma.rn.f32x2 %0, %1, %2, %3;" : "=l"(d) : "l"(a), "l"(b), "l"(c))
#define MUL2(d, a, b)    asm("mul.rn.f32x2 %0, %1, %2;"     : "=l"(d) : "l"(a), "l"(b))

// ============================ HMMA GEMM =====================================
// C[M,N] = (Ah+Al)[M,K] @ (Bh+Bl)[N,K]^T   (3-term split bf16, fp32 accum)
// BM=128, BN=128, BK=32, 2-stage cp.async pipeline (80KB -> 2 CTAs/SM),
// 8 warps (64x32 each). A-fragment ldsm software-pipelined across mt.
#define ROWB     80
#define TILE_B   (128 * ROWB)
#define STAGE_B  (4 * TILE_B)
#define NSTAGE   2
#define GEMM_SMEM (NSTAGE * STAGE_B)   // 81920 B

// MODE: 0 = plain fp32 C, 1 = bias+gelu -> bf16 hi/lo (Ch,Cl), 2 = bias -> C,
//       3 = accumulate into C
template<int MODE>
__global__ __launch_bounds__(256, 2) void gemm_mma(
    const __nv_bfloat16* __restrict__ Ah, const __nv_bfloat16* __restrict__ Al,
    const __nv_bfloat16* __restrict__ Bh, const __nv_bfloat16* __restrict__ Bl,
    const float* __restrict__ bias, float* __restrict__ C,
    __nv_bfloat16* __restrict__ Ch, __nv_bfloat16* __restrict__ Cl,
    int M, int N, int K)
{
    extern __shared__ __align__(128) char smem[];
    uint32_t sb = smem_u32(smem);
    int t    = threadIdx.x;
    int lane = t & 31;
    int wid  = t >> 5;
    int warp_m = wid >> 2;
    int warp_n = wid & 3;
    int row0 = blockIdx.y << 7;
    int col0 = blockIdx.x << 7;

    float acc[4][4][4];
    #pragma unroll
    for (int i = 0; i < 4; i++)
        #pragma unroll
        for (int j = 0; j < 4; j++)
            #pragma unroll
            for (int e = 0; e < 4; e++) acc[i][j][e] = 0.0f;

    const int T = K >> 5;

    // loader: 8 precomputed pointers advanced by +=32 per stage
    int r_ = t >> 2, c_ = t & 3;
    uint32_t so0 = r_ * ROWB + c_ * 16;
    uint32_t so1 = (r_ + 64) * ROWB + c_ * 16;
    const __nv_bfloat16* pAh0 = Ah + (size_t)(row0 + r_) * K + c_ * 8;
    const __nv_bfloat16* pAh1 = pAh0 + (size_t)64 * K;
    const __nv_bfloat16* pAl0 = Al + (size_t)(row0 + r_) * K + c_ * 8;
    const __nv_bfloat16* pAl1 = pAl0 + (size_t)64 * K;
    const __nv_bfloat16* pBh0 = Bh + (size_t)(col0 + r_) * K + c_ * 8;
    const __nv_bfloat16* pBh1 = pBh0 + (size_t)64 * K;
    const __nv_bfloat16* pBl0 = Bl + (size_t)(col0 + r_) * K + c_ * 8;
    const __nv_bfloat16* pBl1 = pBl0 + (size_t)64 * K;

    #define LOAD_STAGE(P) do {                                                \
        uint32_t b_ = sb + (P) * STAGE_B;                                     \
        cp16(b_ + so0,               pAh0);  cp16(b_ + so1,               pAh1); \
        cp16(b_ + TILE_B + so0,      pAl0);  cp16(b_ + TILE_B + so1,      pAl1); \
        cp16(b_ + 2*TILE_B + so0,    pBh0);  cp16(b_ + 2*TILE_B + so1,    pBh1); \
        cp16(b_ + 3*TILE_B + so0,    pBl0);  cp16(b_ + 3*TILE_B + so1,    pBl1); \
        cp_commit();                                                          \
        pAh0 += 32; pAh1 += 32; pAl0 += 32; pAl1 += 32;                       \
        pBh0 += 32; pBh1 += 32; pBl0 += 32; pBl1 += 32;                       \
    } while (0)

    LOAD_STAGE(0);
    LOAD_STAGE(1);

    int lrow = lane & 15, lcol = lane >> 4;

    for (int tt = 0; tt < T; tt++) {
        if (tt + 1 < T) asm volatile("cp.async.wait_group 1;" ::: "memory");
        else            asm volatile("cp.async.wait_group 0;" ::: "memory");
        __syncthreads();

        uint32_t st = sb + (tt & 1) * STAGE_B;
        uint32_t sAh = st;
        uint32_t sAl = st + TILE_B;
        uint32_t sBh = st + 2 * TILE_B;
        uint32_t sBl = st + 3 * TILE_B;

        #pragma unroll
        for (int ks = 0; ks < 2; ks++) {
            uint32_t koff = ks * 32 + lcol * 16;
            uint32_t bh[4][2], bl[4][2];
            #pragma unroll
            for (int bt = 0; bt < 2; bt++) {
                uint32_t rb = (warp_n * 32 + bt * 16 + lrow) * ROWB + koff;
                uint32_t r0, r1, r2, r3;
                ldsm4(r0, r1, r2, r3, sBh + rb);
                bh[bt*2][0] = r0; bh[bt*2][1] = r2;
                bh[bt*2+1][0] = r1; bh[bt*2+1][1] = r3;
                ldsm4(r0, r1, r2, r3, sBl + rb);
                bl[bt*2][0] = r0; bl[bt*2][1] = r2;
                bl[bt*2+1][0] = r1; bl[bt*2+1][1] = r3;
            }

            // software-pipelined A fragments: a[buf][0]=hi, a[buf][1]=lo
            uint32_t a[2][2][4];
            {
                uint32_t ra = (warp_m * 64 + lrow) * ROWB + koff;
                ldsm4(a[0][0][0], a[0][0][1], a[0][0][2], a[0][0][3], sAh + ra);
                ldsm4(a[0][1][0], a[0][1][1], a[0][1][2], a[0][1][3], sAl + ra);
            }
            #pragma unroll
            for (int mt = 0; mt < 4; mt++) {
                if (mt < 3) {
                    uint32_t ra = (warp_m * 64 + (mt + 1) * 16 + lrow) * ROWB + koff;
                    int nb = (mt + 1) & 1;
                    ldsm4(a[nb][0][0], a[nb][0][1], a[nb][0][2], a[nb][0][3], sAh + ra);
                    ldsm4(a[nb][1][0], a[nb][1][1], a[nb][1][2], a[nb][1][3], sAl + ra);
                }
                const uint32_t* ah = a[mt & 1][0];
                const uint32_t* al = a[mt & 1][1];
                #pragma unroll
                for (int nt = 0; nt < 4; nt++) {
                    mma16816(acc[mt][nt], ah, bh[nt]);
                    mma16816(acc[mt][nt], ah, bl[nt]);
                    mma16816(acc[mt][nt], al, bh[nt]);
                }
            }
        }
        __syncthreads();   // compute on this buffer done -> safe to refill
        if (tt + 2 < T) LOAD_STAGE(tt & 1);
    }

    // epilogue
    #pragma unroll
    for (int mt = 0; mt < 4; mt++) {
        int r0g = row0 + warp_m * 64 + mt * 16 + (lane >> 2);
        #pragma unroll
        for (int nt = 0; nt < 4; nt++) {
            int cg = col0 + warp_n * 32 + nt * 8 + (lane & 3) * 2;
            float b0 = 0.f, b1 = 0.f;
            if (MODE == 1 || MODE == 2) { b0 = bias[cg]; b1 = bias[cg + 1]; }
            float v0 = acc[mt][nt][0] + b0;
            float v1 = acc[mt][nt][1] + b1;
            float v2 = acc[mt][nt][2] + b0;
            float v3 = acc[mt][nt][3] + b1;
            if (MODE == 1) {
                v0 = gelu_f(v0); v1 = gelu_f(v1); v2 = gelu_f(v2); v3 = gelu_f(v3);
                size_t i0 = (size_t)r0g * N + cg;
                size_t i1 = (size_t)(r0g + 8) * N + cg;
                __nv_bfloat16 h0 = __float2bfloat16(v0), h1 = __float2bfloat16(v1);
                __nv_bfloat16 h2 = __float2bfloat16(v2), h3 = __float2bfloat16(v3);
                *(__nv_bfloat162*)(Ch + i0) = __halves2bfloat162(h0, h1);
                *(__nv_bfloat162*)(Ch + i1) = __halves2bfloat162(h2, h3);
                *(__nv_bfloat162*)(Cl + i0) = __halves2bfloat162(
                    __float2bfloat16(v0 - __bfloat162float(h0)),
                    __float2bfloat16(v1 - __bfloat162float(h1)));
                *(__nv_bfloat162*)(Cl + i1) = __halves2bfloat162(
                    __float2bfloat16(v2 - __bfloat162float(h2)),
                    __float2bfloat16(v3 - __bfloat162float(h3)));
            } else {
                float* p0 = C + (size_t)r0g * N + cg;
                float* p1 = C + (size_t)(r0g + 8) * N + cg;
                if (MODE == 3) { v0 += p0[0]; v1 += p0[1]; v2 += p1[0]; v3 += p1[1]; }
                p0[0] = v0; p0[1] = v1;
                p1[0] = v2; p1[1] = v3;
            }
        }
    }
}

// ======================= transpose+split: W[K,N] -> Th/Tl[N,K] ==============
__global__ __launch_bounds__(256) void transpose_split_kernel(
    const float* __restrict__ W, __nv_bfloat16* __restrict__ Th,
    __nv_bfloat16* __restrict__ Tl, int K, int N)
{
    __shared__ float tile[32][33];
    int bx = blockIdx.x, by = blockIdx.y;
    int tx = threadIdx.x, ty = threadIdx.y;
    int n_in = bx * 32 + tx;
    for (int j = ty; j < 32; j += 8)
        tile[j][tx] = W[(size_t)(by * 32 + j) * N + n_in];
    __syncthreads();
    for (int jj = ty; jj < 32; jj += 8) {
        float v = tile[tx][jj];
        size_t o = (size_t)(bx * 32 + jj) * K + by * 32 + tx;
        __nv_bfloat16 hi = __float2bfloat16(v);
        Th[o] = hi;
        Tl[o] = __float2bfloat16(v - __bfloat162float(hi));
    }
}

// ---------------- LayerNorm + split (bf16 hi/lo out) ------------------------
__global__ __launch_bounds__(256) void ln_split_kernel(
    const float* __restrict__ x, const float* __restrict__ sc,
    const float* __restrict__ of,
    __nv_bfloat16* __restrict__ yh, __nv_bfloat16* __restrict__ yl)
{
    int row = blockIdx.x;
    int t   = threadIdx.x;
    const float4* xr = (const float4*)(x + (size_t)row * D_MODEL);
    float4 v0 = xr[t];
    float4 v1 = xr[t + 256];
    float s  = v0.x + v0.y + v0.z + v0.w + v1.x + v1.y + v1.z + v1.w;
    float ss = v0.x*v0.x + v0.y*v0.y + v0.z*v0.z + v0.w*v0.w
             + v1.x*v1.x + v1.y*v1.y + v1.z*v1.z + v1.w*v1.w;
    __shared__ float r1[256];
    __shared__ float r2[256];
    r1[t] = s; r2[t] = ss;
    __syncthreads();
    for (int o2 = 128; o2 > 0; o2 >>= 1) {
        if (t < o2) { r1[t] += r1[t + o2]; r2[t] += r2[t + o2]; }
        __syncthreads();
    }
    float mean = r1[0] * (1.0f / D_MODEL);
    float var  = r2[0] * (1.0f / D_MODEL) - mean * mean;
    float rstd = rsqrtf(var + 1e-5f);

    float4 s0 = ((const float4*)sc)[t], s1 = ((const float4*)sc)[t + 256];
    float4 o0 = ((const float4*)of)[t], o1 = ((const float4*)of)[t + 256];
    float y[8];
    y[0] = s0.x * rstd * (v0.x - mean) + o0.x;
    y[1] = s0.y * rstd * (v0.y - mean) + o0.y;
    y[2] = s0.z * rstd * (v0.z - mean) + o0.z;
    y[3] = s0.w * rstd * (v0.w - mean) + o0.w;
    y[4] = s1.x * rstd * (v1.x - mean) + o1.x;
    y[5] = s1.y * rstd * (v1.y - mean) + o1.y;
    y[6] = s1.z * rstd * (v1.z - mean) + o1.z;
    y[7] = s1.w * rstd * (v1.w - mean) + o1.w;

    __nv_bfloat162* H = (__nv_bfloat162*)(yh + (size_t)row * D_MODEL);
    __nv_bfloat162* L = (__nv_bfloat162*)(yl + (size_t)row * D_MODEL);
    #pragma unroll
    for (int g = 0; g < 2; g++) {
        int base2 = g * 512 + 2 * t;
        #pragma unroll
        for (int p = 0; p < 2; p++) {
            float a = y[g*4 + 2*p], b = y[g*4 + 2*p + 1];
            __nv_bfloat16 ha = __float2bfloat16(a), hb = __float2bfloat16(b);
            H[base2 + p] = __halves2bfloat162(ha, hb);
            L[base2 + p] = __halves2bfloat162(
                __float2bfloat16(a - __bfloat162float(ha)),
                __float2bfloat16(b - __bfloat162float(hb)));
        }
    }
}

// ---------------- RoPE on combined qkv (cols [0,4096)), in place -----------
__global__ __launch_bounds__(256) void rope_kernel(float* __restrict__ qkv)
{
    __shared__ double freq[64];
    int t = threadIdx.x;
    if (t < 64) freq[t] = pow(10000.0, -2.0 * t / 128.0);
    __syncthreads();
    int idx = blockIdx.x * 256 + t;
    int row  = idx >> 11;
    int pr   = idx & 2047;
    int slot = pr >> 6;
    int j    = pr & 63;
    int pos  = row & (SEQ - 1);
    size_t base = (size_t)row * LDQKV + slot * DPH + 2 * j;
    double ang = fmod((double)pos * freq[j], 6.283185307179586476925287);
    float fa = (float)ang;
    float sn = sinf(fa), cs = cosf(fa);
    float x0 = qkv[base], x1 = qkv[base + 1];
    qkv[base]     = x0 * cs - x1 * sn;
    qkv[base + 1] = x1 * cs + x0 * sn;
}

// ---------------- Flash attention (causal, +bias), f32x2 packed -------------
// BK=16 keeps smem at 54.5KB.
#define BQ 64
#define BK 16
#define FLASH_SMEM ((64*132 + BK*128 + BK*128 + 64*17) * 4)

__global__ __launch_bounds__(64) void flash_kernel(
    const float* __restrict__ QKV, const float* __restrict__ bias,
    __nv_bfloat16* __restrict__ Oh, __nv_bfloat16* __restrict__ Ol)
{
    extern __shared__ float sm[];
    float* q_sh = sm;                    // 64 x 132 (8B-aligned rows: 132*4=528)
    float* k_sh = q_sh + 64 * 132;       // BK x 128
    float* v_sh = k_sh + BK * 128;       // BK x 128
    float* b_sh = v_sh + BK * 128;       // 64 x 17

    int t  = threadIdx.x;
    int q0 = blockIdx.x * BQ;
    int h  = blockIdx.y;
    int b  = blockIdx.z;
    size_t qb = (size_t)b * SEQ * LDQKV + (size_t)h * DPH;
    size_t kb_ = qb + 2048;
    size_t vb_ = qb + 4096;

    for (int c = t; c < 64 * 32; c += 64) {
        int r = c >> 5, cc = c & 31;
        *(float4*)&q_sh[r * 132 + cc * 4] =
            *(const float4*)&QKV[qb + (size_t)(q0 + r) * LDQKV + cc * 4];
    }

    int qg = q0 + t;
    float m = -1e30f, l = 0.0f;
    u64t o2[64];                          // packed O accumulator (128 floats)
    #pragma unroll
    for (int d = 0; d < 64; d++) o2[d] = 0ull;

    const float scale = 0.08838834764831845f;
    int ntiles = (q0 + BQ) / BK;

    for (int kt = 0; kt < ntiles; kt++) {
        int kbase = kt * BK;
        __syncthreads();
        for (int c = t; c < BK * 32; c += 64) {
            int r = c >> 5, cc = c & 31;
            *(float4*)&k_sh[r * 128 + cc * 4] =
                *(const float4*)&QKV[kb_ + (size_t)(kbase + r) * LDQKV + cc * 4];
            *(float4*)&v_sh[r * 128 + cc * 4] =
                *(const float4*)&QKV[vb_ + (size_t)(kbase + r) * LDQKV + cc * 4];
        }
        for (int i = t; i < BQ * BK; i += 64) {
            int r = i >> 4, c = i & 15;
            b_sh[r * 17 + c] = bias[(size_t)(q0 + r) * SEQ + kbase + c];
        }
        __syncthreads();

        // scores: packed dot products over d (64 pairs)
        u64t acc2[BK];
        #pragma unroll
        for (int j = 0; j < BK; j++) acc2[j] = 0ull;
        const u64t* q2 = (const u64t*)&q_sh[t * 132];
        for (int dc = 0; dc < 64; dc++) {
            u64t qq = q2[dc];
            #pragma unroll
            for (int j = 0; j < BK; j++) {
                u64t kk = *(const u64t*)&k_sh[j * 128 + dc * 2];
                FMA2(acc2[j], qq, kk, acc2[j]);
            }
        }
        float s[BK];
        #pragma unroll
        for (int j = 0; j < BK; j++) {
            float lo, hi;
            unpack2(acc2[j], lo, hi);
            s[j] = lo + hi;
        }

        float tmax = -1e30f;
        #pragma unroll
        for (int j = 0; j < BK; j++) {
            float sv = (kbase + j <= qg) ? s[j] * scale + b_sh[t * 17 + j] : -1e30f;
            s[j] = sv;
            tmax = fmaxf(tmax, sv);
        }
        float mn   = fmaxf(m, tmax);
        float corr = expf(m - mn);
        float ps = 0.0f;
        #pragma unroll
        for (int j = 0; j < BK; j++) {
            float p = expf(s[j] - mn);
            s[j] = p;
            ps += p;
        }
        l = l * corr + ps;
        m = mn;
        u64t cc2 = pack2(corr, corr);
        #pragma unroll
        for (int d = 0; d < 64; d++) MUL2(o2[d], o2[d], cc2);
        for (int j = 0; j < BK; j++) {
            u64t pp = pack2(s[j], s[j]);
            const u64t* v2 = (const u64t*)&v_sh[j * 128];
            #pragma unroll
            for (int dc = 0; dc < 64; dc++)
                FMA2(o2[dc], pp, v2[dc], o2[dc]);
        }
    }

    float inv = 1.0f / l;
    size_t ob = ((size_t)(b * SEQ + qg)) * D_MODEL + (size_t)h * DPH;
    __nv_bfloat162* OH = (__nv_bfloat162*)(Oh + ob);
    __nv_bfloat162* OL = (__nv_bfloat162*)(Ol + ob);
    #pragma unroll
    for (int dc = 0; dc < 64; dc++) {
        float a, c;
        unpack2(o2[dc], a, c);
        a *= inv; c *= inv;
        __nv_bfloat16 ha = __float2bfloat16(a), hc = __float2bfloat16(c);
        OH[dc] = __halves2bfloat162(ha, hc);
        OL[dc] = __halves2bfloat162(
            __float2bfloat16(a - __bfloat162float(ha)),
            __float2bfloat16(c - __bfloat162float(hc)));
    }
}

// ---------------- launch ----------------------------------------------------
extern "C" void kernel_launch(void* const* d_in, const int* in_sizes, int n_in,
                              void* d_out, int out_size)
{
    const float* x         = (const float*)d_in[0];
    const float* attn_bias = (const float*)d_in[1];
    const float* ln_scale  = (const float*)d_in[2];
    const float* ln_offset = (const float*)d_in[3];
    const float* wq        = (const float*)d_in[4];
    const float* wk        = (const float*)d_in[5];
    const float* wv        = (const float*)d_in[6];
    const float* wo        = (const float*)d_in[7];
    const float* w_fc_in   = (const float*)d_in[8];
    const float* b_fc_in   = (const float*)d_in[9];
    const float* w_fc_out  = (const float*)d_in[10];
    const float* b_fc_out  = (const float*)d_in[11];
    float* out = (float*)d_out;

    float* qkv;
    cudaGetSymbolAddress((void**)&qkv, g_qkv);
    __nv_bfloat16 *xnh,*xnl,*hh,*hl,*atth,*attl;
    __nv_bfloat16 *wqkvth,*wqkvtl,*woth,*wotl,*fith,*fitl,*foth,*fotl;
    cudaGetSymbolAddress((void**)&xnh,    g_xnh);
    cudaGetSymbolAddress((void**)&xnl,    g_xnl);
    cudaGetSymbolAddress((void**)&hh,     g_hh);
    cudaGetSymbolAddress((void**)&hl,     g_hl);
    cudaGetSymbolAddress((void**)&atth,   g_atth);
    cudaGetSymbolAddress((void**)&attl,   g_attl);
    cudaGetSymbolAddress((void**)&wqkvth, g_wqkvth);
    cudaGetSymbolAddress((void**)&wqkvtl, g_wqkvtl);
    cudaGetSymbolAddress((void**)&woth,   g_woth);
    cudaGetSymbolAddress((void**)&wotl,   g_wotl);
    cudaGetSymbolAddress((void**)&fith,   g_fith);
    cudaGetSymbolAddress((void**)&fitl,   g_fitl);
    cudaGetSymbolAddress((void**)&foth,   g_foth);
    cudaGetSymbolAddress((void**)&fotl,   g_fotl);

    cudaFuncSetAttribute(gemm_mma<0>, cudaFuncAttributeMaxDynamicSharedMemorySize, GEMM_SMEM);
    cudaFuncSetAttribute(gemm_mma<1>, cudaFuncAttributeMaxDynamicSharedMemorySize, GEMM_SMEM);
    cudaFuncSetAttribute(gemm_mma<2>, cudaFuncAttributeMaxDynamicSharedMemorySize, GEMM_SMEM);
    cudaFuncSetAttribute(gemm_mma<3>, cudaFuncAttributeMaxDynamicSharedMemorySize, GEMM_SMEM);
    cudaFuncSetAttribute(flash_kernel, cudaFuncAttributeMaxDynamicSharedMemorySize, FLASH_SMEM);

    dim3 tb(32, 8);
    const int DD = D_MODEL * D_MODEL;

    // side stream + fork/join events (host objects only; graph-capture safe)
    cudaStream_t s2;
    cudaStreamCreate(&s2);
    cudaEvent_t ev_ln, ev_ffn;
    cudaEventCreateWithFlags(&ev_ln,  cudaEventDisableTiming);
    cudaEventCreateWithFlags(&ev_ffn, cudaEventDisableTiming);

    // ---- main stream: LN, then fork ----
    ln_split_kernel<<<NROWS, 256>>>(x, ln_scale, ln_offset, xnh, xnl);
    cudaEventRecord(ev_ln, 0);

    // ---- side stream: FFN weight transposes + FFN chain ----
    transpose_split_kernel<<<dim3(DFF/32, D_MODEL/32), tb, 0, s2>>>(w_fc_in,  fith, fitl, D_MODEL, DFF);
    transpose_split_kernel<<<dim3(D_MODEL/32, DFF/32), tb, 0, s2>>>(w_fc_out, foth, fotl, DFF, D_MODEL);
    cudaStreamWaitEvent(s2, ev_ln, 0);
    gemm_mma<1><<<dim3(DFF/128, NROWS/128), 256, GEMM_SMEM, s2>>>(
        xnh, xnl, fith, fitl, b_fc_in, nullptr, hh, hl, NROWS, DFF, D_MODEL);
    gemm_mma<2><<<dim3(D_MODEL/128, NROWS/128), 256, GEMM_SMEM, s2>>>(
        hh, hl, foth, fotl, b_fc_out, out, nullptr, nullptr, NROWS, D_MODEL, DFF);
    cudaEventRecord(ev_ffn, s2);

    // ---- main stream: attention chain ----
    transpose_split_kernel<<<dim3(D_MODEL/32, D_MODEL/32), tb>>>(wq, wqkvth,        wqkvtl,        D_MODEL, D_MODEL);
    transpose_split_kernel<<<dim3(D_MODEL/32, D_MODEL/32), tb>>>(wk, wqkvth + DD,   wqkvtl + DD,   D_MODEL, D_MODEL);
    transpose_split_kernel<<<dim3(D_MODEL/32, D_MODEL/32), tb>>>(wv, wqkvth + 2*DD, wqkvtl + 2*DD, D_MODEL, D_MODEL);
    transpose_split_kernel<<<dim3(D_MODEL/32, D_MODEL/32), tb>>>(wo, woth, wotl, D_MODEL, D_MODEL);

    gemm_mma<0><<<dim3(LDQKV/128, NROWS/128), 256, GEMM_SMEM>>>(
        xnh, xnl, wqkvth, wqkvtl, nullptr, qkv, nullptr, nullptr,
        NROWS, LDQKV, D_MODEL);
    rope_kernel<<<(NROWS * 2048) / 256, 256>>>(qkv);
    flash_kernel<<<dim3(SEQ / BQ, NHEADS, BATCH), 64, FLASH_SMEM>>>(
        qkv, attn_bias, atth, attl);

    // ---- join: WO GEMM accumulates into out (written by FFN-out) ----
    cudaStreamWaitEvent(0, ev_ffn, 0);
    gemm_mma<3><<<dim3(D_MODEL/128, NROWS/128), 256, GEMM_SMEM>>>(
        atth, attl, woth, wotl, nullptr, out, nullptr, nullptr, NROWS, D_MODEL, D_MODEL);

    cudaEventDestroy(ev_ln);
    cudaEventDestroy(ev_ffn);
    cudaStreamDestroy(s2);
}